// round 5
// baseline (speedup 1.0000x reference)
#include <cuda_runtime.h>
#include <cstdint>
#include <math.h>

// Problem dims (fixed per reference)
constexpr int B_ = 16;
constexpr int L_ = 1024;
constexpr int D_ = 1024;
#define NEGV (-1e10f)

// ======================= static device scratch ==============================
__device__ __align__(16) float g_scores[(size_t)B_ * L_ * L_]; // scores -> attn (in place)
__device__ __align__(16) float g_c2q[(size_t)B_ * L_ * D_];    // rn(c2q)
__device__ __align__(16) float g_aw[(size_t)B_ * L_ * D_];     // rn(inp * w3)
__device__ __align__(16) float g_inpRN[(size_t)B_ * L_ * D_];  // rn(inp)
__device__ __align__(16) float g_inpT[(size_t)B_ * L_ * D_];   // rn(inp)^T per batch [b][d][j]
__device__ __align__(16) float g_xc[(size_t)B_ * L_ * D_];     // rn(inp * c2q)
__device__ __align__(16) float g_WmT[(size_t)3 * D_ * D_];     // rn(Wm)^T [D, 3D]
__device__ __align__(16) float g_sc[B_ * L_];
__device__ __align__(16) float g_sq[B_ * L_];
__device__ int g_mask_is_byte;

// ======================= small helpers ======================================
__device__ __forceinline__ uint32_t smem_u32(const void* p) {
    uint32_t a;
    asm("{ .reg .u64 t; cvta.to.shared.u64 t, %1; cvt.u32.u64 %0, t; }" : "=r"(a) : "l"(p));
    return a;
}
__device__ __forceinline__ float rn_tf32(float x) {
    uint32_t u;
    asm("cvt.rn.tf32.f32 %0, %1;" : "=r"(u) : "f"(x));
    return __uint_as_float(u);
}
__device__ __forceinline__ void cp16(uint32_t dst, const void* src) {
    asm volatile("cp.async.cg.shared.global [%0], [%1], 16;" :: "r"(dst), "l"(src));
}
__device__ __forceinline__ int mask_at(const void* mask, int idx, int is_byte) {
    if (is_byte) return ((const unsigned char*)mask)[idx] != 0;
    return ((const int*)mask)[idx] != 0;
}
__device__ __forceinline__ void mma_tf32(float* d, const float* a, const float* bf) {
    asm volatile(
        "mma.sync.aligned.m16n8k8.row.col.f32.tf32.tf32.f32 "
        "{%0,%1,%2,%3}, {%4,%5,%6,%7}, {%8,%9}, {%0,%1,%2,%3};"
        : "+f"(d[0]), "+f"(d[1]), "+f"(d[2]), "+f"(d[3])
        : "r"(__float_as_uint(a[0])), "r"(__float_as_uint(a[1])),
          "r"(__float_as_uint(a[2])), "r"(__float_as_uint(a[3])),
          "r"(__float_as_uint(bf[0])), "r"(__float_as_uint(bf[1])));
}

// ======================= mask dtype autodetect ==============================
__global__ void k_detect(const unsigned char* __restrict__ mask) {
    __shared__ int found;
    if (threadIdx.x == 0) found = 0;
    __syncthreads();
    int any = 0;
    for (int p = threadIdx.x; p < B_ * L_; p += blockDim.x)
        if ((p & 3) && mask[p]) any = 1;
    if (any) atomicOr(&found, 1);
    __syncthreads();
    if (threadIdx.x == 0) g_mask_is_byte = found;
}

// ======================= prep: aw, inpRN =====================================
__global__ void k_prep(const float* __restrict__ inp, const float* __restrict__ wsim) {
    int idx = blockIdx.x * blockDim.x + threadIdx.x;      // float4 index
    float4 x = ((const float4*)inp)[idx];
    float4 w = ((const float4*)(wsim + 2 * D_))[idx & 255];
    float4 a, r;
    a.x = rn_tf32(x.x * w.x); a.y = rn_tf32(x.y * w.y);
    a.z = rn_tf32(x.z * w.z); a.w = rn_tf32(x.w * w.w);
    r.x = rn_tf32(x.x); r.y = rn_tf32(x.y); r.z = rn_tf32(x.z); r.w = rn_tf32(x.w);
    ((float4*)g_aw)[idx] = a;
    ((float4*)g_inpRN)[idx] = r;
}

// ======================= s_c, s_q ===========================================
__global__ void k_scsq(const float* __restrict__ inp, const float* __restrict__ wsim) {
    int row = blockIdx.x * (blockDim.x >> 5) + (threadIdx.x >> 5);
    if (row >= B_ * L_) return;
    int lane = threadIdx.x & 31;
    const float* x = inp + (size_t)row * D_;
    float s1 = 0.f, s2 = 0.f;
    for (int d = lane; d < D_; d += 32) {
        float v = x[d];
        s1 += v * wsim[d];
        s2 += v * wsim[D_ + d];
    }
    #pragma unroll
    for (int o = 16; o; o >>= 1) {
        s1 += __shfl_xor_sync(0xffffffffu, s1, o);
        s2 += __shfl_xor_sync(0xffffffffu, s2, o);
    }
    if (lane == 0) { g_sc[row] = s1; g_sq[row] = s2; }
}

// ======================= transposes =========================================
__global__ void k_transpose_inp() {
    __shared__ float t[32][33];
    int b  = blockIdx.z;
    int d0 = blockIdx.x * 32;
    int j0 = blockIdx.y * 32;
    const float* src = g_inpRN + (size_t)b * L_ * D_;
    float* dst = g_inpT + (size_t)b * L_ * D_;
    #pragma unroll
    for (int k = 0; k < 4; k++)
        t[threadIdx.y + 8 * k][threadIdx.x] =
            src[(size_t)(j0 + threadIdx.y + 8 * k) * D_ + d0 + threadIdx.x];
    __syncthreads();
    #pragma unroll
    for (int k = 0; k < 4; k++)
        dst[(size_t)(d0 + threadIdx.y + 8 * k) * L_ + j0 + threadIdx.x] =
            t[threadIdx.x][threadIdx.y + 8 * k];
}

__global__ void k_transpose_wm(const float* __restrict__ Wm) {
    __shared__ float t[32][33];
    int n0 = blockIdx.x * 32;   // col of Wm (D)
    int k0 = blockIdx.y * 32;   // row of Wm (3D)
    #pragma unroll
    for (int k = 0; k < 4; k++)
        t[threadIdx.y + 8 * k][threadIdx.x] =
            rn_tf32(Wm[(size_t)(k0 + threadIdx.y + 8 * k) * D_ + n0 + threadIdx.x]);
    __syncthreads();
    #pragma unroll
    for (int k = 0; k < 4; k++)
        g_WmT[(size_t)(n0 + threadIdx.y + 8 * k) * (3 * D_) + k0 + threadIdx.x] =
            t[threadIdx.x][threadIdx.y + 8 * k];
}

// ======================= softmax (in place, rn output) ======================
__global__ void k_softmax(const void* __restrict__ mask) {
    __shared__ float redmax[8];
    __shared__ float redsum[8];
    int row = blockIdx.x;
    int b   = row >> 10;
    int isb = g_mask_is_byte;
    float* s = g_scores + (size_t)row * L_;
    int t = threadIdx.x;

    float4 v = ((const float4*)s)[t];
    int j0 = t << 2;
    int base = b * L_;
    if (mask_at(mask, base + j0 + 0, isb)) v.x = NEGV;
    if (mask_at(mask, base + j0 + 1, isb)) v.y = NEGV;
    if (mask_at(mask, base + j0 + 2, isb)) v.z = NEGV;
    if (mask_at(mask, base + j0 + 3, isb)) v.w = NEGV;

    float mx = fmaxf(fmaxf(v.x, v.y), fmaxf(v.z, v.w));
    #pragma unroll
    for (int o = 16; o; o >>= 1) mx = fmaxf(mx, __shfl_xor_sync(0xffffffffu, mx, o));
    if ((t & 31) == 0) redmax[t >> 5] = mx;
    __syncthreads();
    mx = fmaxf(fmaxf(fmaxf(redmax[0], redmax[1]), fmaxf(redmax[2], redmax[3])),
               fmaxf(fmaxf(redmax[4], redmax[5]), fmaxf(redmax[6], redmax[7])));

    v.x = __expf(v.x - mx); v.y = __expf(v.y - mx);
    v.z = __expf(v.z - mx); v.w = __expf(v.w - mx);
    float sm = v.x + v.y + v.z + v.w;
    #pragma unroll
    for (int o = 16; o; o >>= 1) sm += __shfl_xor_sync(0xffffffffu, sm, o);
    if ((t & 31) == 0) redsum[t >> 5] = sm;
    __syncthreads();
    sm = redsum[0] + redsum[1] + redsum[2] + redsum[3] +
         redsum[4] + redsum[5] + redsum[6] + redsum[7];
    float inv = 1.0f / sm;
    v.x = rn_tf32(v.x * inv); v.y = rn_tf32(v.y * inv);
    v.z = rn_tf32(v.z * inv); v.w = rn_tf32(v.w * inv);
    ((float4*)s)[t] = v;
}

// ======================= HMMA tf32 GEMM =====================================
// CTA tile M=256, N=128, BK=16. 8 warps (4 M x 2 N), each 64x64 via m16n8k8.
// SMEM [row][k], row stride 20 floats (pad 4) — conflict-free fragment gather.
// 4-stage cp.async pipeline.
// E=1: scores = aw @ inpRN^T (+sc+sq)         [per batch]
// E=2: c2q    = attn @ inpT^T                 [per batch], fused xc epilogue
// E=3: out    = [inpRN|c2q|xc] @ WmT^T (+bias, relu, mask)
constexpr int LDS_ = 20;                        // smem row stride (floats)
constexpr int STAGE_F = (256 + 128) * LDS_;     // floats per stage = 7680
constexpr int STAGE_BYTES = STAGE_F * 4;        // 30720
constexpr int SMEM_TOTAL = 4 * STAGE_BYTES;     // 122880

template <int E>
__global__ __launch_bounds__(256, 1)
void k_gemm_mma(const float* __restrict__ bias, const void* __restrict__ mask,
                float* __restrict__ out) {
    extern __shared__ float smem[];
    uint32_t sbase = smem_u32(smem);
    int tid = threadIdx.x;
    int lane = tid & 31, w = tid >> 5;
    int g = lane >> 2, t = lane & 3;
    int wm = w & 3, wn = w >> 2;                 // warp grid 4 (M) x 2 (N)

    constexpr int NCH = (E == 3) ? 192 : 64;     // K chunks of 16
    constexpr int LDB = (E == 3) ? 3072 : 1024;

    int b  = blockIdx.z;
    int i0 = blockIdx.y * 256;
    int n0 = blockIdx.x * 128;

    const float *A0, *A1 = nullptr, *A2 = nullptr, *Bb;
    if (E == 1) {
        A0 = g_aw    + ((size_t)b << 20) + (size_t)i0 * 1024;
        Bb = g_inpRN + ((size_t)b << 20) + (size_t)n0 * 1024;
    } else if (E == 2) {
        A0 = g_scores + ((size_t)b << 20) + (size_t)i0 * 1024;
        Bb = g_inpT   + ((size_t)b << 20) + (size_t)n0 * 1024;
    } else {
        A0 = g_inpRN + (size_t)i0 * 1024;
        A1 = g_c2q   + (size_t)i0 * 1024;
        A2 = g_xc    + (size_t)i0 * 1024;
        Bb = g_WmT   + (size_t)n0 * 3072;
    }

    // load one K-chunk (16 floats wide) into stage s: A 256 rows, B 128 rows
    auto loadc = [&](int kc, int s) {
        const float* Ab;
        int koff;
        if (E == 3) {
            int seg = kc >> 6;
            koff = (kc & 63) * 16;
            Ab = (seg == 0) ? A0 : (seg == 1) ? A1 : A2;
        } else {
            Ab = A0; koff = kc * 16;
        }
        const float* Bv = Bb + (size_t)kc * 16;
        uint32_t sa = sbase + s * STAGE_BYTES;
        uint32_t sb = sa + 256 * LDS_ * 4;
        #pragma unroll
        for (int r = 0; r < 4; r++) {
            int id = tid + r * 256;
            int row = id >> 2, c4 = id & 3;
            cp16(sa + row * (LDS_ * 4) + c4 * 16, Ab + (size_t)row * 1024 + koff + c4 * 4);
        }
        #pragma unroll
        for (int r = 0; r < 2; r++) {
            int id = tid + r * 256;
            int row = id >> 2, c4 = id & 3;
            cp16(sb + row * (LDS_ * 4) + c4 * 16, Bv + (size_t)row * LDB + c4 * 4);
        }
    };

    float acc[4][8][4];
    #pragma unroll
    for (int i = 0; i < 4; i++)
        #pragma unroll
        for (int j = 0; j < 8; j++)
            #pragma unroll
            for (int q = 0; q < 4; q++) acc[i][j][q] = 0.f;

    // prologue: stages 0..2
    #pragma unroll
    for (int c = 0; c < 3; c++) {
        loadc(c, c);
        asm volatile("cp.async.commit_group;" ::: "memory");
    }

    for (int kc = 0; kc < NCH; kc++) {
        int s = kc & 3;
        asm volatile("cp.async.wait_group 2;" ::: "memory");
        __syncthreads();

        const float* As = smem + s * STAGE_F;
        const float* Bs = As + 256 * LDS_;
        #pragma unroll
        for (int ks = 0; ks < 2; ks++) {
            int kb = ks * 8;
            float af[4][4], bf[8][2];
            #pragma unroll
            for (int mt = 0; mt < 4; mt++) {
                const float* p = As + (wm * 64 + mt * 16 + g) * LDS_ + kb + t;
                af[mt][0] = p[0];
                af[mt][1] = p[8 * LDS_];
                af[mt][2] = p[4];
                af[mt][3] = p[8 * LDS_ + 4];
            }
            #pragma unroll
            for (int nt = 0; nt < 8; nt++) {
                const float* p = Bs + (wn * 64 + nt * 8 + g) * LDS_ + kb + t;
                bf[nt][0] = p[0];
                bf[nt][1] = p[4];
            }
            #pragma unroll
            for (int mt = 0; mt < 4; mt++)
                #pragma unroll
                for (int nt = 0; nt < 8; nt++)
                    mma_tf32(acc[mt][nt], af[mt], bf[nt]);
        }

        int lc = kc + 3;
        if (lc < NCH) loadc(lc, lc & 3);
        asm volatile("cp.async.commit_group;" ::: "memory");
    }

    // ---------------- epilogue ------------------------------------------------
    int isb = (E == 3) ? g_mask_is_byte : 0;
    #pragma unroll
    for (int mt = 0; mt < 4; mt++) {
        int grow0 = i0 + wm * 64 + mt * 16 + g;      // rows grow0, grow0+8
        if (E == 1) {
            float sc0 = g_sc[b * 1024 + grow0];
            float sc1 = g_sc[b * 1024 + grow0 + 8];
            float* c0 = g_scores + ((size_t)b << 20) + (size_t)grow0 * 1024;
            #pragma unroll
            for (int nt = 0; nt < 8; nt++) {
                int gcol = n0 + wn * 64 + nt * 8 + 2 * t;
                float2 sq2 = *(const float2*)(g_sq + b * 1024 + gcol);
                float2 o0 = make_float2(acc[mt][nt][0] + sc0 + sq2.x,
                                        acc[mt][nt][1] + sc0 + sq2.y);
                float2 o1 = make_float2(acc[mt][nt][2] + sc1 + sq2.x,
                                        acc[mt][nt][3] + sc1 + sq2.y);
                *(float2*)(c0 + gcol) = o0;
                *(float2*)(c0 + 8 * 1024 + gcol) = o1;
            }
        } else if (E == 2) {
            size_t base0 = ((size_t)(b * 1024 + grow0)) * 1024;
            #pragma unroll
            for (int nt = 0; nt < 8; nt++) {
                int gcol = n0 + wn * 64 + nt * 8 + 2 * t;
                float2 x0 = *(const float2*)(g_inpRN + base0 + gcol);
                float2 x1 = *(const float2*)(g_inpRN + base0 + 8 * 1024 + gcol);
                float2 c0v = make_float2(rn_tf32(acc[mt][nt][0]), rn_tf32(acc[mt][nt][1]));
                float2 c1v = make_float2(rn_tf32(acc[mt][nt][2]), rn_tf32(acc[mt][nt][3]));
                float2 xc0 = make_float2(rn_tf32(x0.x * c0v.x), rn_tf32(x0.y * c0v.y));
                float2 xc1 = make_float2(rn_tf32(x1.x * c1v.x), rn_tf32(x1.y * c1v.y));
                *(float2*)(g_c2q + base0 + gcol) = c0v;
                *(float2*)(g_c2q + base0 + 8 * 1024 + gcol) = c1v;
                *(float2*)(g_xc + base0 + gcol) = xc0;
                *(float2*)(g_xc + base0 + 8 * 1024 + gcol) = xc1;
            }
        } else {
            int mk0 = mask_at(mask, grow0, isb);
            int mk1 = mask_at(mask, grow0 + 8, isb);
            float* o0 = out + (size_t)grow0 * 1024;
            #pragma unroll
            for (int nt = 0; nt < 8; nt++) {
                int gcol = n0 + wn * 64 + nt * 8 + 2 * t;
                float2 b2 = *(const float2*)(bias + gcol);
                float2 r0, r1;
                r0.x = mk0 ? 0.f : fmaxf(acc[mt][nt][0] + b2.x, 0.f);
                r0.y = mk0 ? 0.f : fmaxf(acc[mt][nt][1] + b2.y, 0.f);
                r1.x = mk1 ? 0.f : fmaxf(acc[mt][nt][2] + b2.x, 0.f);
                r1.y = mk1 ? 0.f : fmaxf(acc[mt][nt][3] + b2.y, 0.f);
                *(float2*)(o0 + gcol) = r0;
                *(float2*)(o0 + 8 * 1024 + gcol) = r1;
            }
        }
    }
}

// ======================= launch =============================================
extern "C" void kernel_launch(void* const* d_in, const int* in_sizes, int n_in,
                              void* d_out, int out_size) {
    const float* inp  = (const float*)d_in[0];
    const void*  mask = d_in[1];
    const float* wsim = (const float*)d_in[2];
    const float* Wm   = (const float*)d_in[3];
    const float* bias = (const float*)d_in[4];
    float* out = (float*)d_out;

    static bool attr_done = false;
    if (!attr_done) {
        cudaFuncSetAttribute(k_gemm_mma<1>, cudaFuncAttributeMaxDynamicSharedMemorySize, SMEM_TOTAL);
        cudaFuncSetAttribute(k_gemm_mma<2>, cudaFuncAttributeMaxDynamicSharedMemorySize, SMEM_TOTAL);
        cudaFuncSetAttribute(k_gemm_mma<3>, cudaFuncAttributeMaxDynamicSharedMemorySize, SMEM_TOTAL);
        attr_done = true;
    }

    k_detect<<<1, 256>>>((const unsigned char*)mask);
    k_prep<<<(B_ * L_ * D_ / 4) / 256, 256>>>(inp, wsim);
    k_scsq<<<(B_ * L_) / 8, 256>>>(inp, wsim);
    k_transpose_inp<<<dim3(32, 32, 16), dim3(32, 8)>>>();
    k_transpose_wm<<<dim3(32, 96), dim3(32, 8)>>>(Wm);

    k_gemm_mma<1><<<dim3(8, 4, 16), 256, SMEM_TOTAL>>>(bias, mask, out);
    k_softmax<<<B_ * L_, 256>>>(mask);
    k_gemm_mma<2><<<dim3(8, 4, 16), 256, SMEM_TOTAL>>>(bias, mask, out);
    k_gemm_mma<3><<<dim3(8, 64, 1), 256, SMEM_TOTAL>>>(bias, mask, out);
}

// round 8
// speedup vs baseline: 2.1042x; 2.1042x over previous
#include <cuda_runtime.h>
#include <cuda_fp16.h>
#include <cstdint>
#include <math.h>

// Problem dims (fixed per reference)
constexpr int B_ = 16;
constexpr int L_ = 1024;
constexpr int D_ = 1024;
#define NEGV (-1e10f)

// ======================= static device scratch ==============================
__device__ __align__(16) float  g_scores[(size_t)B_ * L_ * L_]; // fp32 scores
__device__ __align__(16) __half g_attnH[(size_t)B_ * L_ * L_];  // half attn
__device__ __align__(16) __half g_awH[(size_t)B_ * L_ * D_];    // half(inp*w3)
__device__ __align__(16) __half g_inpH[(size_t)B_ * L_ * D_];   // half(inp)
__device__ __align__(16) __half g_inpTH[(size_t)B_ * L_ * D_];  // half(inp)^T per batch
__device__ __align__(16) __half g_c2qH[(size_t)B_ * L_ * D_];   // half(c2q)
__device__ __align__(16) __half g_xcH[(size_t)B_ * L_ * D_];    // half(inp*c2q)
__device__ __align__(16) __half g_WmTH[(size_t)3 * D_ * D_];    // half(Wm)^T [D, 3D]
__device__ __align__(16) float  g_sc[B_ * L_];
__device__ __align__(16) float  g_sq[B_ * L_];
__device__ int g_mask_is_byte;

// ======================= small helpers ======================================
__device__ __forceinline__ uint32_t smem_u32(const void* p) {
    uint32_t a;
    asm("{ .reg .u64 t; cvta.to.shared.u64 t, %1; cvt.u32.u64 %0, t; }" : "=r"(a) : "l"(p));
    return a;
}
__device__ __forceinline__ void cp16(uint32_t dst, const void* src) {
    asm volatile("cp.async.cg.shared.global [%0], [%1], 16;" :: "r"(dst), "l"(src));
}
__device__ __forceinline__ int mask_at(const void* mask, int idx, int is_byte) {
    if (is_byte) return ((const unsigned char*)mask)[idx] != 0;
    return ((const int*)mask)[idx] != 0;
}
__device__ __forceinline__ void mma_f16(float* d, const uint32_t* a, const uint32_t* b) {
    asm volatile(
        "mma.sync.aligned.m16n8k16.row.col.f32.f16.f16.f32 "
        "{%0,%1,%2,%3}, {%4,%5,%6,%7}, {%8,%9}, {%0,%1,%2,%3};"
        : "+f"(d[0]), "+f"(d[1]), "+f"(d[2]), "+f"(d[3])
        : "r"(a[0]), "r"(a[1]), "r"(a[2]), "r"(a[3]), "r"(b[0]), "r"(b[1]));
}

// ======================= mask dtype autodetect ==============================
__global__ void k_detect(const unsigned char* __restrict__ mask) {
    __shared__ int found;
    if (threadIdx.x == 0) found = 0;
    __syncthreads();
    int any = 0;
    for (int p = threadIdx.x; p < B_ * L_; p += blockDim.x)
        if ((p & 3) && mask[p]) any = 1;
    if (any) atomicOr(&found, 1);
    __syncthreads();
    if (threadIdx.x == 0) g_mask_is_byte = found;
}

// ======================= prep: awH, inpH ====================================
__global__ void k_prep(const float* __restrict__ inp, const float* __restrict__ wsim) {
    int idx = blockIdx.x * blockDim.x + threadIdx.x;      // float4 index
    float4 x = ((const float4*)inp)[idx];
    float4 w = ((const float4*)(wsim + 2 * D_))[idx & 255];
    __half2 a0 = __floats2half2_rn(x.x * w.x, x.y * w.y);
    __half2 a1 = __floats2half2_rn(x.z * w.z, x.w * w.w);
    __half2 r0 = __floats2half2_rn(x.x, x.y);
    __half2 r1 = __floats2half2_rn(x.z, x.w);
    ((__half2*)g_awH)[2 * idx]     = a0;
    ((__half2*)g_awH)[2 * idx + 1] = a1;
    ((__half2*)g_inpH)[2 * idx]     = r0;
    ((__half2*)g_inpH)[2 * idx + 1] = r1;
}

// ======================= s_c, s_q (fp32) ====================================
__global__ void k_scsq(const float* __restrict__ inp, const float* __restrict__ wsim) {
    int row = blockIdx.x * (blockDim.x >> 5) + (threadIdx.x >> 5);
    if (row >= B_ * L_) return;
    int lane = threadIdx.x & 31;
    const float* x = inp + (size_t)row * D_;
    float s1 = 0.f, s2 = 0.f;
    for (int d = lane; d < D_; d += 32) {
        float v = x[d];
        s1 += v * wsim[d];
        s2 += v * wsim[D_ + d];
    }
    #pragma unroll
    for (int o = 16; o; o >>= 1) {
        s1 += __shfl_xor_sync(0xffffffffu, s1, o);
        s2 += __shfl_xor_sync(0xffffffffu, s2, o);
    }
    if (lane == 0) { g_sc[row] = s1; g_sq[row] = s2; }
}

// ======================= transposes (write half) ============================
__global__ void k_transpose_inp(const float* __restrict__ inp) {
    __shared__ float t[32][33];
    int b  = blockIdx.z;
    int d0 = blockIdx.x * 32;
    int j0 = blockIdx.y * 32;
    const float* src = inp + (size_t)b * L_ * D_;
    __half* dst = g_inpTH + (size_t)b * L_ * D_;
    #pragma unroll
    for (int k = 0; k < 4; k++)
        t[threadIdx.y + 8 * k][threadIdx.x] =
            src[(size_t)(j0 + threadIdx.y + 8 * k) * D_ + d0 + threadIdx.x];
    __syncthreads();
    #pragma unroll
    for (int k = 0; k < 4; k++)
        dst[(size_t)(d0 + threadIdx.y + 8 * k) * L_ + j0 + threadIdx.x] =
            __float2half_rn(t[threadIdx.x][threadIdx.y + 8 * k]);
}

__global__ void k_transpose_wm(const float* __restrict__ Wm) {
    __shared__ float t[32][33];
    int n0 = blockIdx.x * 32;   // col of Wm (D)
    int k0 = blockIdx.y * 32;   // row of Wm (3D)
    #pragma unroll
    for (int k = 0; k < 4; k++)
        t[threadIdx.y + 8 * k][threadIdx.x] =
            Wm[(size_t)(k0 + threadIdx.y + 8 * k) * D_ + n0 + threadIdx.x];
    __syncthreads();
    #pragma unroll
    for (int k = 0; k < 4; k++)
        g_WmTH[(size_t)(n0 + threadIdx.y + 8 * k) * (3 * D_) + k0 + threadIdx.x] =
            __float2half_rn(t[threadIdx.x][threadIdx.y + 8 * k]);
}

// ======================= softmax: fp32 scores -> half attn ==================
__global__ void k_softmax(const void* __restrict__ mask) {
    __shared__ float redmax[8];
    __shared__ float redsum[8];
    int row = blockIdx.x;
    int b   = row >> 10;
    int isb = g_mask_is_byte;
    const float* s = g_scores + (size_t)row * L_;
    __half* a = g_attnH + (size_t)row * L_;
    int t = threadIdx.x;

    float4 v = ((const float4*)s)[t];
    int j0 = t << 2;
    int base = b * L_;
    if (mask_at(mask, base + j0 + 0, isb)) v.x = NEGV;
    if (mask_at(mask, base + j0 + 1, isb)) v.y = NEGV;
    if (mask_at(mask, base + j0 + 2, isb)) v.z = NEGV;
    if (mask_at(mask, base + j0 + 3, isb)) v.w = NEGV;

    float mx = fmaxf(fmaxf(v.x, v.y), fmaxf(v.z, v.w));
    #pragma unroll
    for (int o = 16; o; o >>= 1) mx = fmaxf(mx, __shfl_xor_sync(0xffffffffu, mx, o));
    if ((t & 31) == 0) redmax[t >> 5] = mx;
    __syncthreads();
    mx = fmaxf(fmaxf(fmaxf(redmax[0], redmax[1]), fmaxf(redmax[2], redmax[3])),
               fmaxf(fmaxf(redmax[4], redmax[5]), fmaxf(redmax[6], redmax[7])));

    v.x = __expf(v.x - mx); v.y = __expf(v.y - mx);
    v.z = __expf(v.z - mx); v.w = __expf(v.w - mx);
    float sm = v.x + v.y + v.z + v.w;
    #pragma unroll
    for (int o = 16; o; o >>= 1) sm += __shfl_xor_sync(0xffffffffu, sm, o);
    if ((t & 31) == 0) redsum[t >> 5] = sm;
    __syncthreads();
    sm = redsum[0] + redsum[1] + redsum[2] + redsum[3] +
         redsum[4] + redsum[5] + redsum[6] + redsum[7];
    float inv = 1.0f / sm;
    ((__half2*)a)[2 * t]     = __floats2half2_rn(v.x * inv, v.y * inv);
    ((__half2*)a)[2 * t + 1] = __floats2half2_rn(v.z * inv, v.w * inv);
}

// ======================= fp16 HMMA GEMM =====================================
// CTA tile M=128, N=128, BK=32 halves. 8 warps (2 M x 4 N), each 64x32 via
// m16n8k16. SMEM rows of 64B data padded to 80B stride — fragment gathers
// hit 32 distinct banks (g*20 + t mod 32 all distinct). 4-stage cp.async.
// E=1: scores(fp32) = awH @ inpH^T (+sc+sq)     [per batch]
// E=2: c2qH/xcH     = attnH @ inpTH^T           [per batch]
// E=3: out(fp32)    = [inpH|c2qH|xcH] @ WmTH^T (+bias, relu, mask)
constexpr int ROWB = 80;                         // smem row stride (bytes)
constexpr int STAGE_BYTES = 2 * 128 * ROWB;      // 20480
constexpr int SMEM_TOTAL = 4 * STAGE_BYTES;      // 81920

template <int E>
__global__ __launch_bounds__(256, 2)
void k_gemm_mma(const float* __restrict__ bias, const void* __restrict__ mask,
                float* __restrict__ out) {
    extern __shared__ char smem[];
    uint32_t sbase = smem_u32(smem);
    int tid = threadIdx.x;
    int lane = tid & 31, w = tid >> 5;
    int g = lane >> 2, t = lane & 3;
    int wm = w & 1, wn = w >> 1;                 // warp grid 2 (M) x 4 (N)

    constexpr int NCH = (E == 3) ? 96 : 32;      // K chunks of 32 halves
    constexpr int LDB = (E == 3) ? 3072 : 1024;

    int b  = blockIdx.z;
    int i0 = blockIdx.y * 128;
    int n0 = blockIdx.x * 128;

    const __half *A0, *A1 = nullptr, *A2 = nullptr, *Bb;
    if (E == 1) {
        A0 = g_awH  + ((size_t)b << 20) + (size_t)i0 * 1024;
        Bb = g_inpH + ((size_t)b << 20) + (size_t)n0 * 1024;
    } else if (E == 2) {
        A0 = g_attnH + ((size_t)b << 20) + (size_t)i0 * 1024;
        Bb = g_inpTH + ((size_t)b << 20) + (size_t)n0 * 1024;
    } else {
        A0 = g_inpH + (size_t)i0 * 1024;
        A1 = g_c2qH + (size_t)i0 * 1024;
        A2 = g_xcH  + (size_t)i0 * 1024;
        Bb = g_WmTH + (size_t)n0 * 3072;
    }

    // load one K-chunk (32 halves = 64B/row) into stage s: A 128 rows, B 128 rows
    auto loadc = [&](int kc, int s) {
        const __half* Ab;
        int koff;
        if (E == 3) {
            int seg = kc >> 5;
            koff = (kc & 31) * 32;
            Ab = (seg == 0) ? A0 : (seg == 1) ? A1 : A2;
        } else {
            Ab = A0; koff = kc * 32;
        }
        const __half* Bv = Bb + (size_t)kc * 32;
        uint32_t sa = sbase + s * STAGE_BYTES;
        uint32_t sb = sa + 128 * ROWB;
        // 512 16B chunks each for A and B; 2 per thread each
        #pragma unroll
        for (int r = 0; r < 2; r++) {
            int id = tid + r * 256;
            int row = id >> 2, c4 = id & 3;
            cp16(sa + row * ROWB + c4 * 16, Ab + (size_t)row * 1024 + koff + c4 * 8);
        }
        #pragma unroll
        for (int r = 0; r < 2; r++) {
            int id = tid + r * 256;
            int row = id >> 2, c4 = id & 3;
            cp16(sb + row * ROWB + c4 * 16, Bv + (size_t)row * LDB + c4 * 8);
        }
    };

    float acc[4][4][4];
    #pragma unroll
    for (int i = 0; i < 4; i++)
        #pragma unroll
        for (int j = 0; j < 4; j++)
            #pragma unroll
            for (int q = 0; q < 4; q++) acc[i][j][q] = 0.f;

    // prologue: stages 0..2
    #pragma unroll
    for (int c = 0; c < 3; c++) {
        loadc(c, c);
        asm volatile("cp.async.commit_group;" ::: "memory");
    }

    for (int kc = 0; kc < NCH; kc++) {
        int s = kc & 3;
        asm volatile("cp.async.wait_group 2;" ::: "memory");
        __syncthreads();

        const char* As = smem + s * STAGE_BYTES;
        const char* Bs = As + 128 * ROWB;
        #pragma unroll
        for (int ks = 0; ks < 2; ks++) {
            int kb = ks * 16;                       // halves
            uint32_t af[4][4], bf[4][2];
            #pragma unroll
            for (int mt = 0; mt < 4; mt++) {
                const char* p = As + (wm * 64 + mt * 16 + g) * ROWB + (kb + 2 * t) * 2;
                af[mt][0] = *(const uint32_t*)(p);
                af[mt][1] = *(const uint32_t*)(p + 8 * ROWB);
                af[mt][2] = *(const uint32_t*)(p + 16);
                af[mt][3] = *(const uint32_t*)(p + 8 * ROWB + 16);
            }
            #pragma unroll
            for (int nt = 0; nt < 4; nt++) {
                const char* p = Bs + (wn * 32 + nt * 8 + g) * ROWB + (kb + 2 * t) * 2;
                bf[nt][0] = *(const uint32_t*)(p);
                bf[nt][1] = *(const uint32_t*)(p + 16);
            }
            #pragma unroll
            for (int mt = 0; mt < 4; mt++)
                #pragma unroll
                for (int nt = 0; nt < 4; nt++)
                    mma_f16(acc[mt][nt], af[mt], bf[nt]);
        }

        int lc = kc + 3;
        if (lc < NCH) loadc(lc, lc & 3);
        asm volatile("cp.async.commit_group;" ::: "memory");
    }

    // ---------------- epilogue ------------------------------------------------
    int isb = (E == 3) ? g_mask_is_byte : 0;
    #pragma unroll
    for (int mt = 0; mt < 4; mt++) {
        int grow0 = i0 + wm * 64 + mt * 16 + g;      // rows grow0, grow0+8
        if (E == 1) {
            float sc0 = g_sc[b * 1024 + grow0];
            float sc1 = g_sc[b * 1024 + grow0 + 8];
            float* c0 = g_scores + ((size_t)b << 20) + (size_t)grow0 * 1024;
            #pragma unroll
            for (int nt = 0; nt < 4; nt++) {
                int gcol = n0 + wn * 32 + nt * 8 + 2 * t;
                float2 sq2 = *(const float2*)(g_sq + b * 1024 + gcol);
                float2 o0 = make_float2(acc[mt][nt][0] + sc0 + sq2.x,
                                        acc[mt][nt][1] + sc0 + sq2.y);
                float2 o1 = make_float2(acc[mt][nt][2] + sc1 + sq2.x,
                                        acc[mt][nt][3] + sc1 + sq2.y);
                *(float2*)(c0 + gcol) = o0;
                *(float2*)(c0 + 8 * 1024 + gcol) = o1;
            }
        } else if (E == 2) {
            size_t base0 = ((size_t)(b * 1024 + grow0)) * 1024;
            #pragma unroll
            for (int nt = 0; nt < 4; nt++) {
                int gcol = n0 + wn * 32 + nt * 8 + 2 * t;
                float2 x0 = __half22float2(*(const __half2*)(g_inpH + base0 + gcol));
                float2 x1 = __half22float2(*(const __half2*)(g_inpH + base0 + 8 * 1024 + gcol));
                __half2 c0h = __floats2half2_rn(acc[mt][nt][0], acc[mt][nt][1]);
                __half2 c1h = __floats2half2_rn(acc[mt][nt][2], acc[mt][nt][3]);
                float2 c0f = __half22float2(c0h);
                float2 c1f = __half22float2(c1h);
                __half2 xc0 = __floats2half2_rn(x0.x * c0f.x, x0.y * c0f.y);
                __half2 xc1 = __floats2half2_rn(x1.x * c1f.x, x1.y * c1f.y);
                *(__half2*)(g_c2qH + base0 + gcol) = c0h;
                *(__half2*)(g_c2qH + base0 + 8 * 1024 + gcol) = c1h;
                *(__half2*)(g_xcH + base0 + gcol) = xc0;
                *(__half2*)(g_xcH + base0 + 8 * 1024 + gcol) = xc1;
            }
        } else {
            int mk0 = mask_at(mask, grow0, isb);
            int mk1 = mask_at(mask, grow0 + 8, isb);
            float* o0 = out + (size_t)grow0 * 1024;
            #pragma unroll
            for (int nt = 0; nt < 4; nt++) {
                int gcol = n0 + wn * 32 + nt * 8 + 2 * t;
                float2 b2 = *(const float2*)(bias + gcol);
                float2 r0, r1;
                r0.x = mk0 ? 0.f : fmaxf(acc[mt][nt][0] + b2.x, 0.f);
                r0.y = mk0 ? 0.f : fmaxf(acc[mt][nt][1] + b2.y, 0.f);
                r1.x = mk1 ? 0.f : fmaxf(acc[mt][nt][2] + b2.x, 0.f);
                r1.y = mk1 ? 0.f : fmaxf(acc[mt][nt][3] + b2.y, 0.f);
                *(float2*)(o0 + gcol) = r0;
                *(float2*)(o0 + 8 * 1024 + gcol) = r1;
            }
        }
    }
}

// ======================= launch =============================================
extern "C" void kernel_launch(void* const* d_in, const int* in_sizes, int n_in,
                              void* d_out, int out_size) {
    const float* inp  = (const float*)d_in[0];
    const void*  mask = d_in[1];
    const float* wsim = (const float*)d_in[2];
    const float* Wm   = (const float*)d_in[3];
    const float* bias = (const float*)d_in[4];
    float* out = (float*)d_out;

    static bool attr_done = false;
    if (!attr_done) {
        cudaFuncSetAttribute(k_gemm_mma<1>, cudaFuncAttributeMaxDynamicSharedMemorySize, SMEM_TOTAL);
        cudaFuncSetAttribute(k_gemm_mma<2>, cudaFuncAttributeMaxDynamicSharedMemorySize, SMEM_TOTAL);
        cudaFuncSetAttribute(k_gemm_mma<3>, cudaFuncAttributeMaxDynamicSharedMemorySize, SMEM_TOTAL);
        attr_done = true;
    }

    k_detect<<<1, 256>>>((const unsigned char*)mask);
    k_prep<<<(B_ * L_ * D_ / 4) / 256, 256>>>(inp, wsim);
    k_scsq<<<(B_ * L_) / 8, 256>>>(inp, wsim);
    k_transpose_inp<<<dim3(32, 32, 16), dim3(32, 8)>>>(inp);
    k_transpose_wm<<<dim3(32, 96), dim3(32, 8)>>>(Wm);

    k_gemm_mma<1><<<dim3(8, 8, 16), 256, SMEM_TOTAL>>>(bias, mask, out);
    k_softmax<<<B_ * L_, 256>>>(mask);
    k_gemm_mma<2><<<dim3(8, 8, 16), 256, SMEM_TOTAL>>>(bias, mask, out);
    k_gemm_mma<3><<<dim3(8, 128, 1), 256, SMEM_TOTAL>>>(bias, mask, out);
}

// round 10
// speedup vs baseline: 2.2801x; 1.0836x over previous
#include <cuda_runtime.h>
#include <cuda_fp16.h>
#include <cstdint>
#include <math.h>

// Problem dims (fixed per reference)
constexpr int B_ = 16;
constexpr int L_ = 1024;
constexpr int D_ = 1024;
#define NEGV (-1e10f)

// ======================= static device scratch ==============================
__device__ __align__(16) float  g_scores[(size_t)B_ * L_ * L_]; // fp32 scores
__device__ __align__(16) __half g_attnH[(size_t)B_ * L_ * L_];  // half attn
__device__ __align__(16) __half g_awH[(size_t)B_ * L_ * D_];    // half(inp*w3)
__device__ __align__(16) __half g_inpH[(size_t)B_ * L_ * D_];   // half(inp)
__device__ __align__(16) __half g_inpTH[(size_t)B_ * L_ * D_];  // half(inp)^T per batch
__device__ __align__(16) __half g_c2qH[(size_t)B_ * L_ * D_];   // half(c2q)
__device__ __align__(16) __half g_xcH[(size_t)B_ * L_ * D_];    // half(inp*c2q)
__device__ __align__(16) __half g_WmTH[(size_t)3 * D_ * D_];    // half(Wm)^T [D, 3D]
__device__ __align__(16) float  g_sc[B_ * L_];
__device__ __align__(16) float  g_sq[B_ * L_];
__device__ int g_mask_is_byte;

// ======================= small helpers ======================================
__device__ __forceinline__ uint32_t smem_u32(const void* p) {
    uint32_t a;
    asm("{ .reg .u64 t; cvta.to.shared.u64 t, %1; cvt.u32.u64 %0, t; }" : "=r"(a) : "l"(p));
    return a;
}
__device__ __forceinline__ void cp16(uint32_t dst, const void* src) {
    asm volatile("cp.async.cg.shared.global [%0], [%1], 16;" :: "r"(dst), "l"(src));
}
__device__ __forceinline__ int mask_at(const void* mask, int idx, int is_byte) {
    if (is_byte) return ((const unsigned char*)mask)[idx] != 0;
    return ((const int*)mask)[idx] != 0;
}
__device__ __forceinline__ void mma_f16(float* d, const uint32_t* a, const uint32_t* b) {
    asm volatile(
        "mma.sync.aligned.m16n8k16.row.col.f32.f16.f16.f32 "
        "{%0,%1,%2,%3}, {%4,%5,%6,%7}, {%8,%9}, {%0,%1,%2,%3};"
        : "+f"(d[0]), "+f"(d[1]), "+f"(d[2]), "+f"(d[3])
        : "r"(a[0]), "r"(a[1]), "r"(a[2]), "r"(a[3]), "r"(b[0]), "r"(b[1]));
}
__device__ __forceinline__ void ldsm_x4(uint32_t addr, uint32_t& r0, uint32_t& r1,
                                        uint32_t& r2, uint32_t& r3) {
    asm volatile("ldmatrix.sync.aligned.m8n8.x4.shared.b16 {%0,%1,%2,%3}, [%4];"
                 : "=r"(r0), "=r"(r1), "=r"(r2), "=r"(r3) : "r"(addr));
}

// ======================= mask dtype autodetect ==============================
__global__ void k_detect(const unsigned char* __restrict__ mask) {
    __shared__ int found;
    if (threadIdx.x == 0) found = 0;
    __syncthreads();
    int any = 0;
    for (int p = threadIdx.x; p < B_ * L_; p += blockDim.x)
        if ((p & 3) && mask[p]) any = 1;
    if (any) atomicOr(&found, 1);
    __syncthreads();
    if (threadIdx.x == 0) g_mask_is_byte = found;
}

// ======================= prep: awH, inpH ====================================
__global__ void k_prep(const float* __restrict__ inp, const float* __restrict__ wsim) {
    int idx = blockIdx.x * blockDim.x + threadIdx.x;      // float4 index
    float4 x = ((const float4*)inp)[idx];
    float4 w = ((const float4*)(wsim + 2 * D_))[idx & 255];
    __half2 a0 = __floats2half2_rn(x.x * w.x, x.y * w.y);
    __half2 a1 = __floats2half2_rn(x.z * w.z, x.w * w.w);
    __half2 r0 = __floats2half2_rn(x.x, x.y);
    __half2 r1 = __floats2half2_rn(x.z, x.w);
    ((__half2*)g_awH)[2 * idx]     = a0;
    ((__half2*)g_awH)[2 * idx + 1] = a1;
    ((__half2*)g_inpH)[2 * idx]     = r0;
    ((__half2*)g_inpH)[2 * idx + 1] = r1;
}

// ======================= s_c, s_q (fp32) ====================================
__global__ void k_scsq(const float* __restrict__ inp, const float* __restrict__ wsim) {
    int row = blockIdx.x * (blockDim.x >> 5) + (threadIdx.x >> 5);
    if (row >= B_ * L_) return;
    int lane = threadIdx.x & 31;
    const float* x = inp + (size_t)row * D_;
    float s1 = 0.f, s2 = 0.f;
    for (int d = lane; d < D_; d += 32) {
        float v = x[d];
        s1 += v * wsim[d];
        s2 += v * wsim[D_ + d];
    }
    #pragma unroll
    for (int o = 16; o; o >>= 1) {
        s1 += __shfl_xor_sync(0xffffffffu, s1, o);
        s2 += __shfl_xor_sync(0xffffffffu, s2, o);
    }
    if (lane == 0) { g_sc[row] = s1; g_sq[row] = s2; }
}

// ======================= transposes (write half) ============================
__global__ void k_transpose_inp(const float* __restrict__ inp) {
    __shared__ float t[32][33];
    int b  = blockIdx.z;
    int d0 = blockIdx.x * 32;
    int j0 = blockIdx.y * 32;
    const float* src = inp + (size_t)b * L_ * D_;
    __half* dst = g_inpTH + (size_t)b * L_ * D_;
    #pragma unroll
    for (int k = 0; k < 4; k++)
        t[threadIdx.y + 8 * k][threadIdx.x] =
            src[(size_t)(j0 + threadIdx.y + 8 * k) * D_ + d0 + threadIdx.x];
    __syncthreads();
    #pragma unroll
    for (int k = 0; k < 4; k++)
        dst[(size_t)(d0 + threadIdx.y + 8 * k) * L_ + j0 + threadIdx.x] =
            __float2half_rn(t[threadIdx.x][threadIdx.y + 8 * k]);
}

__global__ void k_transpose_wm(const float* __restrict__ Wm) {
    __shared__ float t[32][33];
    int n0 = blockIdx.x * 32;   // col of Wm (D)
    int k0 = blockIdx.y * 32;   // row of Wm (3D)
    #pragma unroll
    for (int k = 0; k < 4; k++)
        t[threadIdx.y + 8 * k][threadIdx.x] =
            Wm[(size_t)(k0 + threadIdx.y + 8 * k) * D_ + n0 + threadIdx.x];
    __syncthreads();
    #pragma unroll
    for (int k = 0; k < 4; k++)
        g_WmTH[(size_t)(n0 + threadIdx.y + 8 * k) * (3 * D_) + k0 + threadIdx.x] =
            __float2half_rn(t[threadIdx.x][threadIdx.y + 8 * k]);
}

// ======================= softmax: fp32 scores -> half attn ==================
__global__ void k_softmax(const void* __restrict__ mask) {
    __shared__ float redmax[8];
    __shared__ float redsum[8];
    int row = blockIdx.x;
    int b   = row >> 10;
    int isb = g_mask_is_byte;
    const float* s = g_scores + (size_t)row * L_;
    __half* a = g_attnH + (size_t)row * L_;
    int t = threadIdx.x;

    float4 v = ((const float4*)s)[t];
    int j0 = t << 2;
    int base = b * L_;
    if (mask_at(mask, base + j0 + 0, isb)) v.x = NEGV;
    if (mask_at(mask, base + j0 + 1, isb)) v.y = NEGV;
    if (mask_at(mask, base + j0 + 2, isb)) v.z = NEGV;
    if (mask_at(mask, base + j0 + 3, isb)) v.w = NEGV;

    float mx = fmaxf(fmaxf(v.x, v.y), fmaxf(v.z, v.w));
    #pragma unroll
    for (int o = 16; o; o >>= 1) mx = fmaxf(mx, __shfl_xor_sync(0xffffffffu, mx, o));
    if ((t & 31) == 0) redmax[t >> 5] = mx;
    __syncthreads();
    mx = fmaxf(fmaxf(fmaxf(redmax[0], redmax[1]), fmaxf(redmax[2], redmax[3])),
               fmaxf(fmaxf(redmax[4], redmax[5]), fmaxf(redmax[6], redmax[7])));

    v.x = __expf(v.x - mx); v.y = __expf(v.y - mx);
    v.z = __expf(v.z - mx); v.w = __expf(v.w - mx);
    float sm = v.x + v.y + v.z + v.w;
    #pragma unroll
    for (int o = 16; o; o >>= 1) sm += __shfl_xor_sync(0xffffffffu, sm, o);
    if ((t & 31) == 0) redsum[t >> 5] = sm;
    __syncthreads();
    sm = redsum[0] + redsum[1] + redsum[2] + redsum[3] +
         redsum[4] + redsum[5] + redsum[6] + redsum[7];
    float inv = 1.0f / sm;
    ((__half2*)a)[2 * t]     = __floats2half2_rn(v.x * inv, v.y * inv);
    ((__half2*)a)[2 * t + 1] = __floats2half2_rn(v.z * inv, v.w * inv);
}

// ======================= fp16 HMMA GEMM (ldmatrix) ==========================
// CTA tile M=128, N=128, BK=32 halves. 8 warps (2 M x 4 N), each 64x32 via
// m16n8k16. SMEM rows 64B data padded to 80B stride — conflict-free for both
// ldmatrix phases and cp.async stores. 4-stage cp.async pipeline.
// Fragment loads via ldmatrix.m8n8.x4: 6 LDSM per ks-step vs 24 LDS.32.
// E=1: scores(fp32) = awH @ inpH^T (+sc+sq)     [per batch]
// E=2: c2qH/xcH     = attnH @ inpTH^T           [per batch]
// E=3: out(fp32)    = [inpH|c2qH|xcH] @ WmTH^T (+bias, relu, mask)
constexpr int ROWB = 80;                         // smem row stride (bytes)
constexpr int STAGE_BYTES = 2 * 128 * ROWB;      // 20480
constexpr int SMEM_TOTAL = 4 * STAGE_BYTES;      // 81920

template <int E>
__global__ __launch_bounds__(256, 2)
void k_gemm_mma(const float* __restrict__ bias, const void* __restrict__ mask,
                float* __restrict__ out) {
    extern __shared__ char smem[];
    uint32_t sbase = smem_u32(smem);
    int tid = threadIdx.x;
    int lane = tid & 31, w = tid >> 5;
    int g = lane >> 2, t = lane & 3;
    int wm = w & 1, wn = w >> 1;                 // warp grid 2 (M) x 4 (N)

    constexpr int NCH = (E == 3) ? 96 : 32;      // K chunks of 32 halves
    constexpr int LDB = (E == 3) ? 3072 : 1024;

    int b  = blockIdx.z;
    int i0 = blockIdx.y * 128;
    int n0 = blockIdx.x * 128;

    const __half *A0, *A1 = nullptr, *A2 = nullptr, *Bb;
    if (E == 1) {
        A0 = g_awH  + ((size_t)b << 20) + (size_t)i0 * 1024;
        Bb = g_inpH + ((size_t)b << 20) + (size_t)n0 * 1024;
    } else if (E == 2) {
        A0 = g_attnH + ((size_t)b << 20) + (size_t)i0 * 1024;
        Bb = g_inpTH + ((size_t)b << 20) + (size_t)n0 * 1024;
    } else {
        A0 = g_inpH + (size_t)i0 * 1024;
        A1 = g_c2qH + (size_t)i0 * 1024;
        A2 = g_xcH  + (size_t)i0 * 1024;
        Bb = g_WmTH + (size_t)n0 * 3072;
    }

    // ldmatrix per-lane address offsets (within a stage)
    // A (x4: mats = {rows+0,+0B},{rows+8,+0B},{rows+0,+16B},{rows+8,+16B}):
    int mat = lane >> 3, mrow = lane & 7;
    uint32_t offA = (uint32_t)(wm * 64 + (mat & 1) * 8 + mrow) * ROWB + (mat >> 1) * 16;
    // B (x4: mats = {nt0,+0B},{nt0,+16B},{nt1,+0B},{nt1,+16B}):
    uint32_t offB = (uint32_t)(wn * 32 + (mat >> 1) * 8 + mrow) * ROWB + (mat & 1) * 16;

    // load one K-chunk (32 halves = 64B/row) into stage s: A 128 rows, B 128 rows
    auto loadc = [&](int kc, int s) {
        const __half* Ab;
        int koff;
        if (E == 3) {
            int seg = kc >> 5;
            koff = (kc & 31) * 32;
            Ab = (seg == 0) ? A0 : (seg == 1) ? A1 : A2;
        } else {
            Ab = A0; koff = kc * 32;
        }
        const __half* Bv = Bb + (size_t)kc * 32;
        uint32_t sa = sbase + s * STAGE_BYTES;
        uint32_t sb = sa + 128 * ROWB;
        #pragma unroll
        for (int r = 0; r < 2; r++) {
            int id = tid + r * 256;
            int row = id >> 2, c4 = id & 3;
            cp16(sa + row * ROWB + c4 * 16, Ab + (size_t)row * 1024 + koff + c4 * 8);
        }
        #pragma unroll
        for (int r = 0; r < 2; r++) {
            int id = tid + r * 256;
            int row = id >> 2, c4 = id & 3;
            cp16(sb + row * ROWB + c4 * 16, Bv + (size_t)row * LDB + c4 * 8);
        }
    };

    float acc[4][4][4];
    #pragma unroll
    for (int i = 0; i < 4; i++)
        #pragma unroll
        for (int j = 0; j < 4; j++)
            #pragma unroll
            for (int q = 0; q < 4; q++) acc[i][j][q] = 0.f;

    // prologue: stages 0..2
    #pragma unroll
    for (int c = 0; c < 3; c++) {
        loadc(c, c);
        asm volatile("cp.async.commit_group;" ::: "memory");
    }

    for (int kc = 0; kc < NCH; kc++) {
        int s = kc & 3;
        asm volatile("cp.async.wait_group 2;" ::: "memory");
        __syncthreads();

        uint32_t As = sbase + s * STAGE_BYTES;
        uint32_t Bs = As + 128 * ROWB;
        #pragma unroll
        for (int ks = 0; ks < 2; ks++) {
            uint32_t kbyte = ks * 32;               // 16 halves * 2B
            uint32_t af[4][4], bf[4][2];
            #pragma unroll
            for (int mt = 0; mt < 4; mt++)
                ldsm_x4(As + offA + mt * 16 * ROWB + kbyte,
                        af[mt][0], af[mt][1], af[mt][2], af[mt][3]);
            #pragma unroll
            for (int np = 0; np < 2; np++)
                ldsm_x4(Bs + offB + np * 16 * ROWB + kbyte,
                        bf[2 * np][0], bf[2 * np][1],
                        bf[2 * np + 1][0], bf[2 * np + 1][1]);
            #pragma unroll
            for (int mt = 0; mt < 4; mt++)
                #pragma unroll
                for (int nt = 0; nt < 4; nt++)
                    mma_f16(acc[mt][nt], af[mt], bf[nt]);
        }

        int lc = kc + 3;
        if (lc < NCH) loadc(lc, lc & 3);
        asm volatile("cp.async.commit_group;" ::: "memory");
    }

    // ---------------- epilogue ------------------------------------------------
    int isb = (E == 3) ? g_mask_is_byte : 0;
    #pragma unroll
    for (int mt = 0; mt < 4; mt++) {
        int grow0 = i0 + wm * 64 + mt * 16 + g;      // rows grow0, grow0+8
        if (E == 1) {
            float sc0 = g_sc[b * 1024 + grow0];
            float sc1 = g_sc[b * 1024 + grow0 + 8];
            float* c0 = g_scores + ((size_t)b << 20) + (size_t)grow0 * 1024;
            #pragma unroll
            for (int nt = 0; nt < 4; nt++) {
                int gcol = n0 + wn * 32 + nt * 8 + 2 * t;
                float2 sq2 = *(const float2*)(g_sq + b * 1024 + gcol);
                float2 o0 = make_float2(acc[mt][nt][0] + sc0 + sq2.x,
                                        acc[mt][nt][1] + sc0 + sq2.y);
                float2 o1 = make_float2(acc[mt][nt][2] + sc1 + sq2.x,
                                        acc[mt][nt][3] + sc1 + sq2.y);
                *(float2*)(c0 + gcol) = o0;
                *(float2*)(c0 + 8 * 1024 + gcol) = o1;
            }
        } else if (E == 2) {
            size_t base0 = ((size_t)(b * 1024 + grow0)) * 1024;
            #pragma unroll
            for (int nt = 0; nt < 4; nt++) {
                int gcol = n0 + wn * 32 + nt * 8 + 2 * t;
                float2 x0 = __half22float2(*(const __half2*)(g_inpH + base0 + gcol));
                float2 x1 = __half22float2(*(const __half2*)(g_inpH + base0 + 8 * 1024 + gcol));
                __half2 c0h = __floats2half2_rn(acc[mt][nt][0], acc[mt][nt][1]);
                __half2 c1h = __floats2half2_rn(acc[mt][nt][2], acc[mt][nt][3]);
                float2 c0f = __half22float2(c0h);
                float2 c1f = __half22float2(c1h);
                __half2 xc0 = __floats2half2_rn(x0.x * c0f.x, x0.y * c0f.y);
                __half2 xc1 = __floats2half2_rn(x1.x * c1f.x, x1.y * c1f.y);
                *(__half2*)(g_c2qH + base0 + gcol) = c0h;
                *(__half2*)(g_c2qH + base0 + 8 * 1024 + gcol) = c1h;
                *(__half2*)(g_xcH + base0 + gcol) = xc0;
                *(__half2*)(g_xcH + base0 + 8 * 1024 + gcol) = xc1;
            }
        } else {
            int mk0 = mask_at(mask, grow0, isb);
            int mk1 = mask_at(mask, grow0 + 8, isb);
            float* o0 = out + (size_t)grow0 * 1024;
            #pragma unroll
            for (int nt = 0; nt < 4; nt++) {
                int gcol = n0 + wn * 32 + nt * 8 + 2 * t;
                float2 b2 = *(const float2*)(bias + gcol);
                float2 r0, r1;
                r0.x = mk0 ? 0.f : fmaxf(acc[mt][nt][0] + b2.x, 0.f);
                r0.y = mk0 ? 0.f : fmaxf(acc[mt][nt][1] + b2.y, 0.f);
                r1.x = mk1 ? 0.f : fmaxf(acc[mt][nt][2] + b2.x, 0.f);
                r1.y = mk1 ? 0.f : fmaxf(acc[mt][nt][3] + b2.y, 0.f);
                *(float2*)(o0 + gcol) = r0;
                *(float2*)(o0 + 8 * 1024 + gcol) = r1;
            }
        }
    }
}

// ======================= launch =============================================
extern "C" void kernel_launch(void* const* d_in, const int* in_sizes, int n_in,
                              void* d_out, int out_size) {
    const float* inp  = (const float*)d_in[0];
    const void*  mask = d_in[1];
    const float* wsim = (const float*)d_in[2];
    const float* Wm   = (const float*)d_in[3];
    const float* bias = (const float*)d_in[4];
    float* out = (float*)d_out;

    static bool attr_done = false;
    if (!attr_done) {
        cudaFuncSetAttribute(k_gemm_mma<1>, cudaFuncAttributeMaxDynamicSharedMemorySize, SMEM_TOTAL);
        cudaFuncSetAttribute(k_gemm_mma<2>, cudaFuncAttributeMaxDynamicSharedMemorySize, SMEM_TOTAL);
        cudaFuncSetAttribute(k_gemm_mma<3>, cudaFuncAttributeMaxDynamicSharedMemorySize, SMEM_TOTAL);
        attr_done = true;
    }

    k_detect<<<1, 256>>>((const unsigned char*)mask);
    k_prep<<<(B_ * L_ * D_ / 4) / 256, 256>>>(inp, wsim);
    k_scsq<<<(B_ * L_) / 8, 256>>>(inp, wsim);
    k_transpose_inp<<<dim3(32, 32, 16), dim3(32, 8)>>>(inp);
    k_transpose_wm<<<dim3(32, 96), dim3(32, 8)>>>(Wm);

    k_gemm_mma<1><<<dim3(8, 8, 16), 256, SMEM_TOTAL>>>(bias, mask, out);
    k_softmax<<<B_ * L_, 256>>>(mask);
    k_gemm_mma<2><<<dim3(8, 8, 16), 256, SMEM_TOTAL>>>(bias, mask, out);
    k_gemm_mma<3><<<dim3(8, 128, 1), 256, SMEM_TOTAL>>>(bias, mask, out);
}

// round 11
// speedup vs baseline: 2.5684x; 1.1264x over previous
#include <cuda_runtime.h>
#include <cuda_fp16.h>
#include <cstdint>
#include <math.h>

// Problem dims (fixed per reference)
constexpr int B_ = 16;
constexpr int L_ = 1024;
constexpr int D_ = 1024;
#define NEGV (-1e10f)

// ======================= static device scratch ==============================
__device__ __align__(16) float  g_scores[(size_t)B_ * L_ * L_]; // fp32 scores
__device__ __align__(16) __half g_attnH[(size_t)B_ * L_ * L_];  // half attn
__device__ __align__(16) __half g_awH[(size_t)B_ * L_ * D_];    // half(inp*w3)
__device__ __align__(16) __half g_inpH[(size_t)B_ * L_ * D_];   // half(inp)
__device__ __align__(16) __half g_inpTH[(size_t)B_ * L_ * D_];  // half(inp)^T per batch
__device__ __align__(16) __half g_c2qH[(size_t)B_ * L_ * D_];   // half(c2q)
__device__ __align__(16) __half g_xcH[(size_t)B_ * L_ * D_];    // half(inp*c2q)
__device__ __align__(16) __half g_WmTH[(size_t)3 * D_ * D_];    // half(Wm)^T [D, 3D]
__device__ __align__(16) float  g_sq[B_ * L_];
__device__ int g_mask_is_byte;

// ======================= small helpers ======================================
__device__ __forceinline__ uint32_t smem_u32(const void* p) {
    uint32_t a;
    asm("{ .reg .u64 t; cvta.to.shared.u64 t, %1; cvt.u32.u64 %0, t; }" : "=r"(a) : "l"(p));
    return a;
}
__device__ __forceinline__ void cp16(uint32_t dst, const void* src) {
    asm volatile("cp.async.cg.shared.global [%0], [%1], 16;" :: "r"(dst), "l"(src));
}
__device__ __forceinline__ int mask_at(const void* mask, int idx, int is_byte) {
    if (is_byte) return ((const unsigned char*)mask)[idx] != 0;
    return ((const int*)mask)[idx] != 0;
}
__device__ __forceinline__ void mma_f16(float* d, const uint32_t* a, const uint32_t* b) {
    asm volatile(
        "mma.sync.aligned.m16n8k16.row.col.f32.f16.f16.f32 "
        "{%0,%1,%2,%3}, {%4,%5,%6,%7}, {%8,%9}, {%0,%1,%2,%3};"
        : "+f"(d[0]), "+f"(d[1]), "+f"(d[2]), "+f"(d[3])
        : "r"(a[0]), "r"(a[1]), "r"(a[2]), "r"(a[3]), "r"(b[0]), "r"(b[1]));
}
__device__ __forceinline__ void ldsm_x4(uint32_t addr, uint32_t& r0, uint32_t& r1,
                                        uint32_t& r2, uint32_t& r3) {
    asm volatile("ldmatrix.sync.aligned.m8n8.x4.shared.b16 {%0,%1,%2,%3}, [%4];"
                 : "=r"(r0), "=r"(r1), "=r"(r2), "=r"(r3) : "r"(addr));
}

// ======================= mask dtype autodetect ==============================
__global__ void k_detect(const unsigned char* __restrict__ mask) {
    __shared__ int found;
    if (threadIdx.x == 0) found = 0;
    __syncthreads();
    int any = 0;
    for (int p = threadIdx.x; p < B_ * L_; p += blockDim.x)
        if ((p & 3) && mask[p]) any = 1;
    if (any) atomicOr(&found, 1);
    __syncthreads();
    if (threadIdx.x == 0) g_mask_is_byte = found;
}

// ======================= prep: awH, inpH ====================================
__global__ void k_prep(const float* __restrict__ inp, const float* __restrict__ wsim) {
    int idx = blockIdx.x * blockDim.x + threadIdx.x;      // float4 index
    float4 x = ((const float4*)inp)[idx];
    float4 w = ((const float4*)(wsim + 2 * D_))[idx & 255];
    __half2 a0 = __floats2half2_rn(x.x * w.x, x.y * w.y);
    __half2 a1 = __floats2half2_rn(x.z * w.z, x.w * w.w);
    __half2 r0 = __floats2half2_rn(x.x, x.y);
    __half2 r1 = __floats2half2_rn(x.z, x.w);
    ((__half2*)g_awH)[2 * idx]     = a0;
    ((__half2*)g_awH)[2 * idx + 1] = a1;
    ((__half2*)g_inpH)[2 * idx]     = r0;
    ((__half2*)g_inpH)[2 * idx + 1] = r1;
}

// ======================= s_q (fp32) =========================================
// NOTE: s_c (per-row constant) cancels under softmax and is dropped entirely.
__global__ void k_sq(const float* __restrict__ inp, const float* __restrict__ wsim) {
    int row = blockIdx.x * (blockDim.x >> 5) + (threadIdx.x >> 5);
    if (row >= B_ * L_) return;
    int lane = threadIdx.x & 31;
    const float* x = inp + (size_t)row * D_;
    float s2 = 0.f;
    for (int d = lane; d < D_; d += 32)
        s2 += x[d] * wsim[D_ + d];
    #pragma unroll
    for (int o = 16; o; o >>= 1)
        s2 += __shfl_xor_sync(0xffffffffu, s2, o);
    if (lane == 0) g_sq[row] = s2;
}

// ======================= transposes (write half) ============================
__global__ void k_transpose_inp(const float* __restrict__ inp) {
    __shared__ float t[32][33];
    int b  = blockIdx.z;
    int d0 = blockIdx.x * 32;
    int j0 = blockIdx.y * 32;
    const float* src = inp + (size_t)b * L_ * D_;
    __half* dst = g_inpTH + (size_t)b * L_ * D_;
    #pragma unroll
    for (int k = 0; k < 4; k++)
        t[threadIdx.y + 8 * k][threadIdx.x] =
            src[(size_t)(j0 + threadIdx.y + 8 * k) * D_ + d0 + threadIdx.x];
    __syncthreads();
    #pragma unroll
    for (int k = 0; k < 4; k++)
        dst[(size_t)(d0 + threadIdx.y + 8 * k) * L_ + j0 + threadIdx.x] =
            __float2half_rn(t[threadIdx.x][threadIdx.y + 8 * k]);
}

__global__ void k_transpose_wm(const float* __restrict__ Wm) {
    __shared__ float t[32][33];
    int n0 = blockIdx.x * 32;   // col of Wm (D)
    int k0 = blockIdx.y * 32;   // row of Wm (3D)
    #pragma unroll
    for (int k = 0; k < 4; k++)
        t[threadIdx.y + 8 * k][threadIdx.x] =
            Wm[(size_t)(k0 + threadIdx.y + 8 * k) * D_ + n0 + threadIdx.x];
    __syncthreads();
    #pragma unroll
    for (int k = 0; k < 4; k++)
        g_WmTH[(size_t)(n0 + threadIdx.y + 8 * k) * (3 * D_) + k0 + threadIdx.x] =
            __float2half_rn(t[threadIdx.x][threadIdx.y + 8 * k]);
}

// ======================= softmax: fp32 scores -> half attn ==================
__global__ void k_softmax(const void* __restrict__ mask) {
    __shared__ float redmax[8];
    __shared__ float redsum[8];
    int row = blockIdx.x;
    int b   = row >> 10;
    int isb = g_mask_is_byte;
    const float* s = g_scores + (size_t)row * L_;
    __half* a = g_attnH + (size_t)row * L_;
    int t = threadIdx.x;

    float4 v = ((const float4*)s)[t];
    int j0 = t << 2;
    int base = b * L_;
    if (mask_at(mask, base + j0 + 0, isb)) v.x = NEGV;
    if (mask_at(mask, base + j0 + 1, isb)) v.y = NEGV;
    if (mask_at(mask, base + j0 + 2, isb)) v.z = NEGV;
    if (mask_at(mask, base + j0 + 3, isb)) v.w = NEGV;

    float mx = fmaxf(fmaxf(v.x, v.y), fmaxf(v.z, v.w));
    #pragma unroll
    for (int o = 16; o; o >>= 1) mx = fmaxf(mx, __shfl_xor_sync(0xffffffffu, mx, o));
    if ((t & 31) == 0) redmax[t >> 5] = mx;
    __syncthreads();
    mx = fmaxf(fmaxf(fmaxf(redmax[0], redmax[1]), fmaxf(redmax[2], redmax[3])),
               fmaxf(fmaxf(redmax[4], redmax[5]), fmaxf(redmax[6], redmax[7])));

    v.x = __expf(v.x - mx); v.y = __expf(v.y - mx);
    v.z = __expf(v.z - mx); v.w = __expf(v.w - mx);
    float sm = v.x + v.y + v.z + v.w;
    #pragma unroll
    for (int o = 16; o; o >>= 1) sm += __shfl_xor_sync(0xffffffffu, sm, o);
    if ((t & 31) == 0) redsum[t >> 5] = sm;
    __syncthreads();
    sm = redsum[0] + redsum[1] + redsum[2] + redsum[3] +
         redsum[4] + redsum[5] + redsum[6] + redsum[7];
    float inv = 1.0f / sm;
    ((__half2*)a)[2 * t]     = __floats2half2_rn(v.x * inv, v.y * inv);
    ((__half2*)a)[2 * t + 1] = __floats2half2_rn(v.z * inv, v.w * inv);
}

// ======================= fp16 HMMA GEMM (ldmatrix, BK=64) ===================
// CTA tile M=128, N=128, BK=64 halves. 8 warps (2 M x 4 N), each 64x32 via
// m16n8k16. SMEM rows 128B data padded to 144B stride — conflict-free for
// ldmatrix (banks 4r mod 32). 3-stage cp.async pipeline, occupancy 2.
// E=1: scores(fp32) = awH @ inpH^T (+sq)        [per batch]
// E=2: c2qH/xcH     = attnH @ inpTH^T           [per batch]
// E=3: out(fp32)    = [inpH|c2qH|xcH] @ WmTH^T (+bias, relu, mask)
constexpr int ROWB = 144;                        // smem row stride (bytes)
constexpr int STAGE_BYTES = 2 * 128 * ROWB;      // 36864
constexpr int SMEM_TOTAL = 3 * STAGE_BYTES;      // 110592

template <int E>
__global__ __launch_bounds__(256, 2)
void k_gemm_mma(const float* __restrict__ bias, const void* __restrict__ mask,
                float* __restrict__ out) {
    extern __shared__ char smem[];
    uint32_t sbase = smem_u32(smem);
    int tid = threadIdx.x;
    int lane = tid & 31, w = tid >> 5;
    int g = lane >> 2, t = lane & 3;
    int wm = w & 1, wn = w >> 1;                 // warp grid 2 (M) x 4 (N)

    constexpr int NCH = (E == 3) ? 48 : 16;      // K chunks of 64 halves
    constexpr int LDB = (E == 3) ? 3072 : 1024;

    int b  = blockIdx.z;
    int i0 = blockIdx.y * 128;
    int n0 = blockIdx.x * 128;

    const __half *A0, *A1 = nullptr, *A2 = nullptr, *Bb;
    if (E == 1) {
        A0 = g_awH  + ((size_t)b << 20) + (size_t)i0 * 1024;
        Bb = g_inpH + ((size_t)b << 20) + (size_t)n0 * 1024;
    } else if (E == 2) {
        A0 = g_attnH + ((size_t)b << 20) + (size_t)i0 * 1024;
        Bb = g_inpTH + ((size_t)b << 20) + (size_t)n0 * 1024;
    } else {
        A0 = g_inpH + (size_t)i0 * 1024;
        A1 = g_c2qH + (size_t)i0 * 1024;
        A2 = g_xcH  + (size_t)i0 * 1024;
        Bb = g_WmTH + (size_t)n0 * 3072;
    }

    // ldmatrix per-lane address offsets (within a stage)
    int mat = lane >> 3, mrow = lane & 7;
    // A (x4: {rows+0,+0B},{rows+8,+0B},{rows+0,+16B},{rows+8,+16B})
    uint32_t offA = (uint32_t)(wm * 64 + (mat & 1) * 8 + mrow) * ROWB + (mat >> 1) * 16;
    // B (x4: {nt0,+0B},{nt0,+16B},{nt1,+0B},{nt1,+16B})
    uint32_t offB = (uint32_t)(wn * 32 + (mat >> 1) * 8 + mrow) * ROWB + (mat & 1) * 16;

    // load one K-chunk (64 halves = 128B/row): A 128 rows, B 128 rows
    auto loadc = [&](int kc, int s) {
        const __half* Ab;
        int koff;
        if (E == 3) {
            int seg = kc >> 4;
            koff = (kc & 15) * 64;
            Ab = (seg == 0) ? A0 : (seg == 1) ? A1 : A2;
        } else {
            Ab = A0; koff = kc * 64;
        }
        const __half* Bv = Bb + (size_t)kc * 64;
        uint32_t sa = sbase + s * STAGE_BYTES;
        uint32_t sb = sa + 128 * ROWB;
        #pragma unroll
        for (int r = 0; r < 4; r++) {
            int id = tid + r * 256;
            int row = id >> 3, c8 = id & 7;
            cp16(sa + row * ROWB + c8 * 16, Ab + (size_t)row * 1024 + koff + c8 * 8);
        }
        #pragma unroll
        for (int r = 0; r < 4; r++) {
            int id = tid + r * 256;
            int row = id >> 3, c8 = id & 7;
            cp16(sb + row * ROWB + c8 * 16, Bv + (size_t)row * LDB + c8 * 8);
        }
    };

    float acc[4][4][4];
    #pragma unroll
    for (int i = 0; i < 4; i++)
        #pragma unroll
        for (int j = 0; j < 4; j++)
            #pragma unroll
            for (int q = 0; q < 4; q++) acc[i][j][q] = 0.f;

    // prologue: stages 0..1
    #pragma unroll
    for (int c = 0; c < 2; c++) {
        loadc(c, c);
        asm volatile("cp.async.commit_group;" ::: "memory");
    }

    int stage = 0;
    for (int kc = 0; kc < NCH; kc++) {
        asm volatile("cp.async.wait_group 1;" ::: "memory");
        __syncthreads();

        uint32_t As = sbase + stage * STAGE_BYTES;
        uint32_t Bs = As + 128 * ROWB;
        #pragma unroll
        for (int ks = 0; ks < 4; ks++) {
            uint32_t kbyte = ks * 32;               // 16 halves * 2B
            uint32_t af[4][4], bf[4][2];
            #pragma unroll
            for (int mt = 0; mt < 4; mt++)
                ldsm_x4(As + offA + mt * 16 * ROWB + kbyte,
                        af[mt][0], af[mt][1], af[mt][2], af[mt][3]);
            #pragma unroll
            for (int np = 0; np < 2; np++)
                ldsm_x4(Bs + offB + np * 16 * ROWB + kbyte,
                        bf[2 * np][0], bf[2 * np][1],
                        bf[2 * np + 1][0], bf[2 * np + 1][1]);
            #pragma unroll
            for (int mt = 0; mt < 4; mt++)
                #pragma unroll
                for (int nt = 0; nt < 4; nt++)
                    mma_f16(acc[mt][nt], af[mt], bf[nt]);
        }

        int lc = kc + 2;
        if (lc < NCH) {
            int ls = stage + 2; if (ls >= 3) ls -= 3;
            loadc(lc, ls);
        }
        asm volatile("cp.async.commit_group;" ::: "memory");
        if (++stage == 3) stage = 0;
    }

    // ---------------- epilogue ------------------------------------------------
    int isb = (E == 3) ? g_mask_is_byte : 0;
    #pragma unroll
    for (int mt = 0; mt < 4; mt++) {
        int grow0 = i0 + wm * 64 + mt * 16 + g;      // rows grow0, grow0+8
        if (E == 1) {
            float* c0 = g_scores + ((size_t)b << 20) + (size_t)grow0 * 1024;
            #pragma unroll
            for (int nt = 0; nt < 4; nt++) {
                int gcol = n0 + wn * 32 + nt * 8 + 2 * t;
                float2 sq2 = *(const float2*)(g_sq + b * 1024 + gcol);
                float2 o0 = make_float2(acc[mt][nt][0] + sq2.x,
                                        acc[mt][nt][1] + sq2.y);
                float2 o1 = make_float2(acc[mt][nt][2] + sq2.x,
                                        acc[mt][nt][3] + sq2.y);
                *(float2*)(c0 + gcol) = o0;
                *(float2*)(c0 + 8 * 1024 + gcol) = o1;
            }
        } else if (E == 2) {
            size_t base0 = ((size_t)(b * 1024 + grow0)) * 1024;
            #pragma unroll
            for (int nt = 0; nt < 4; nt++) {
                int gcol = n0 + wn * 32 + nt * 8 + 2 * t;
                float2 x0 = __half22float2(*(const __half2*)(g_inpH + base0 + gcol));
                float2 x1 = __half22float2(*(const __half2*)(g_inpH + base0 + 8 * 1024 + gcol));
                __half2 c0h = __floats2half2_rn(acc[mt][nt][0], acc[mt][nt][1]);
                __half2 c1h = __floats2half2_rn(acc[mt][nt][2], acc[mt][nt][3]);
                float2 c0f = __half22float2(c0h);
                float2 c1f = __half22float2(c1h);
                __half2 xc0 = __floats2half2_rn(x0.x * c0f.x, x0.y * c0f.y);
                __half2 xc1 = __floats2half2_rn(x1.x * c1f.x, x1.y * c1f.y);
                *(__half2*)(g_c2qH + base0 + gcol) = c0h;
                *(__half2*)(g_c2qH + base0 + 8 * 1024 + gcol) = c1h;
                *(__half2*)(g_xcH + base0 + gcol) = xc0;
                *(__half2*)(g_xcH + base0 + 8 * 1024 + gcol) = xc1;
            }
        } else {
            int mk0 = mask_at(mask, grow0, isb);
            int mk1 = mask_at(mask, grow0 + 8, isb);
            float* o0 = out + (size_t)grow0 * 1024;
            #pragma unroll
            for (int nt = 0; nt < 4; nt++) {
                int gcol = n0 + wn * 32 + nt * 8 + 2 * t;
                float2 b2 = *(const float2*)(bias + gcol);
                float2 r0, r1;
                r0.x = mk0 ? 0.f : fmaxf(acc[mt][nt][0] + b2.x, 0.f);
                r0.y = mk0 ? 0.f : fmaxf(acc[mt][nt][1] + b2.y, 0.f);
                r1.x = mk1 ? 0.f : fmaxf(acc[mt][nt][2] + b2.x, 0.f);
                r1.y = mk1 ? 0.f : fmaxf(acc[mt][nt][3] + b2.y, 0.f);
                *(float2*)(o0 + gcol) = r0;
                *(float2*)(o0 + 8 * 1024 + gcol) = r1;
            }
        }
    }
}

// ======================= launch =============================================
extern "C" void kernel_launch(void* const* d_in, const int* in_sizes, int n_in,
                              void* d_out, int out_size) {
    const float* inp  = (const float*)d_in[0];
    const void*  mask = d_in[1];
    const float* wsim = (const float*)d_in[2];
    const float* Wm   = (const float*)d_in[3];
    const float* bias = (const float*)d_in[4];
    float* out = (float*)d_out;

    static bool attr_done = false;
    if (!attr_done) {
        cudaFuncSetAttribute(k_gemm_mma<1>, cudaFuncAttributeMaxDynamicSharedMemorySize, SMEM_TOTAL);
        cudaFuncSetAttribute(k_gemm_mma<2>, cudaFuncAttributeMaxDynamicSharedMemorySize, SMEM_TOTAL);
        cudaFuncSetAttribute(k_gemm_mma<3>, cudaFuncAttributeMaxDynamicSharedMemorySize, SMEM_TOTAL);
        attr_done = true;
    }

    k_detect<<<1, 256>>>((const unsigned char*)mask);
    k_prep<<<(B_ * L_ * D_ / 4) / 256, 256>>>(inp, wsim);
    k_sq<<<(B_ * L_) / 8, 256>>>(inp, wsim);
    k_transpose_inp<<<dim3(32, 32, 16), dim3(32, 8)>>>(inp);
    k_transpose_wm<<<dim3(32, 96), dim3(32, 8)>>>(Wm);

    k_gemm_mma<1><<<dim3(8, 8, 16), 256, SMEM_TOTAL>>>(bias, mask, out);
    k_softmax<<<B_ * L_, 256>>>(mask);
    k_gemm_mma<2><<<dim3(8, 8, 16), 256, SMEM_TOTAL>>>(bias, mask, out);
    k_gemm_mma<3><<<dim3(8, 128, 1), 256, SMEM_TOTAL>>>(bias, mask, out);
}